// round 9
// baseline (speedup 1.0000x reference)
#include <cuda_runtime.h>
#include <cuda_fp16.h>
#include <cstdint>

#define BATCH 16
#define SEQ   2048
#define DIN   4096
#define DOUT  4096
#define RANK  64
#define KSPLIT 4
#define KRANGE (DIN / KSPLIT)     // 1024
#define OSPLIT 4
#define SCALING (1.0f/64.0f)

// ---------------- device scratch (no allocations allowed) -------------------
__device__ unsigned short g_Bh[(size_t)BATCH * RANK * DIN];   // B fp16 [b][r][k]
__device__ unsigned short g_Ah[(size_t)BATCH * DOUT * RANK];  // A fp16 [b][o][r]
// Y partials: [ks][b][nt] tiles of [128][64] fp32  (4*16*16*8192 = 33.5 MB)
__device__ float g_Yp[(size_t)KSPLIT * BATCH * 16 * 128 * 64];

// ---------------- helpers ----------------------------------------------------
__device__ __forceinline__ uint32_t smem_u32(const void* p) {
    uint32_t a;
    asm("{ .reg .u64 t; cvta.to.shared.u64 t, %1; cvt.u32.u64 %0, t; }"
        : "=r"(a) : "l"(p));
    return a;
}
#define SW64(o)  ((uint32_t)(o) ^ ((((uint32_t)(o)) >> 3) & 0x30))
#define SW128(o) ((uint32_t)(o) ^ ((((uint32_t)(o)) >> 3) & 0x70))

__device__ __forceinline__ uint32_t h2u(__half2 h) {
    return *reinterpret_cast<uint32_t*>(&h);
}

// cp.async (portable PTX, sm_80+)
#define CP_ASYNC16(dst, src) \
    asm volatile("cp.async.cg.shared.global [%0], [%1], 16;" :: "r"(dst), "l"(src))
#define CP_COMMIT() asm volatile("cp.async.commit_group;" ::: "memory")
#define CP_WAIT1()  asm volatile("cp.async.wait_group 1;" ::: "memory")

// ldmatrix x4 (portable PTX, sm_75+)
#define LDSM4(r0, r1, r2, r3, addr) \
    asm volatile("ldmatrix.sync.aligned.m8n8.x4.shared.b16 {%0,%1,%2,%3}, [%4];" \
        : "=r"(r0), "=r"(r1), "=r"(r2), "=r"(r3) : "r"(addr))

// mma.sync fp16, fp32 accumulate (portable PTX, sm_80+)
#define MMA(d, a, b0v, b1v) \
    asm volatile("mma.sync.aligned.m16n8k16.row.col.f32.f16.f16.f32 " \
        "{%0,%1,%2,%3}, {%4,%5,%6,%7}, {%8,%9}, {%0,%1,%2,%3};" \
        : "+f"((d)[0]), "+f"((d)[1]), "+f"((d)[2]), "+f"((d)[3]) \
        : "r"((a)[0]), "r"((a)[1]), "r"((a)[2]), "r"((a)[3]), "r"(b0v), "r"(b1v))

// ---------------------------------------------------------------------------
// adapter id resolution (int64 or int32 buffer; reads first 64 bytes only)
// ---------------------------------------------------------------------------
__device__ __forceinline__ int resolve_id(const int* raw, int b) {
    bool odd_zero = true;
    #pragma unroll
    for (int i = 1; i < 16; i += 2) odd_zero &= (raw[i] == 0);
    return odd_zero ? raw[2 * b] : raw[b];
}

// ---------------------------------------------------------------------------
// Convert requested A/B adapter slices to fp16.
// grid (128, BATCH, 2), block 256. z=0: B, z=1: A.
// ---------------------------------------------------------------------------
__global__ __launch_bounds__(256) void split_kernel(const float* __restrict__ Am,
                                                    const float* __restrict__ Bm,
                                                    const int* __restrict__ ids) {
    const int b = blockIdx.y;
    const int aid = resolve_id(ids, b);
    const int which = blockIdx.z;
    const size_t i8 = (size_t)blockIdx.x * 256 + threadIdx.x;
    const size_t PER = (size_t)RANK * DIN;
    const float* src = (which ? Am : Bm) + (size_t)aid * PER + i8 * 8;
    unsigned short* dh = (which ? g_Ah : g_Bh) + (size_t)b * PER + i8 * 8;
    float4 v0 = *(const float4*)src;
    float4 v1 = *(const float4*)(src + 4);
    *(uint4*)dh = make_uint4(
        h2u(__floats2half2_rn(v0.x, v0.y)), h2u(__floats2half2_rn(v0.z, v0.w)),
        h2u(__floats2half2_rn(v1.x, v1.y)), h2u(__floats2half2_rn(v1.z, v1.w)));
}

// ---------------------------------------------------------------------------
// Stage 1: Y_partial[ks][b][nt] = fp16(x[128 rows, K-slice]) @ fp16(B slice)^T
// grid (16 nt, 16 b, 4 ks), 256 thr, 8 warps (warp owns 16 n-rows).
// cp.async 3-buffer pipeline over 32 chunks of K=32.
// smem (73728): 3 x-bufs [128][40] fp32 @0, 3 B-bufs @61440.
// ---------------------------------------------------------------------------
#define CK 32
#define NCH (KRANGE / CK)         // 32
#define XS 40
#define XBUF_SZ (128 * XS * 4)    // 20480
#define BBUF_SZ (64 * CK * 2)     // 4096
#define S_B 61440
#define SMEM1 73728

__global__ __launch_bounds__(256, 3) void stage1_kernel(const float* __restrict__ x) {
    extern __shared__ char smem[];
    const uint32_t sb = smem_u32(smem);
    const int tid = threadIdx.x;
    const int w = tid >> 5;
    const int lane = tid & 31;
    const int nt = blockIdx.x;
    const int b = blockIdx.y;
    const int ks = blockIdx.z;

    const float* xp = x + ((size_t)b * SEQ + (size_t)nt * 128) * DIN + (size_t)ks * KRANGE;
    const unsigned short* bhp = g_Bh + (size_t)b * RANK * DIN + (size_t)ks * KRANGE;

    const int lrow = lane & 15;
    const int lkb = (lane >> 4) * 16;

    float acc[8][4];
    #pragma unroll
    for (int i = 0; i < 8; i++)
        #pragma unroll
        for (int j = 0; j < 4; j++) acc[i][j] = 0.f;

    auto issue1 = [&](int ch) {
        if (ch < NCH) {
            const int buf = ch % 3;
            const int k0 = ch * CK;
            #pragma unroll
            for (int t = 0; t < 4; t++) {
                int idx = tid + t * 256;
                int row = idx >> 3, f4 = idx & 7;
                CP_ASYNC16(sb + buf * XBUF_SZ + row * (XS * 4) + f4 * 16,
                           xp + (size_t)row * DIN + k0 + f4 * 4);
            }
            {
                int row = tid >> 2, f4 = tid & 3;
                CP_ASYNC16(sb + S_B + buf * BBUF_SZ + SW64(row * 64 + f4 * 16),
                           bhp + (size_t)row * DIN + k0 + f4 * 8);
            }
        }
        CP_COMMIT();
    };

    issue1(0);
    issue1(1);
    const int xr = w * 16 + (lane >> 2);
    const int xc = (lane & 3) * 2;
    for (int c = 0; c < NCH; c++) {
        CP_WAIT1();
        __syncthreads();
        issue1(c + 2);
        const float* xb = (const float*)(smem + (c % 3) * XBUF_SZ);
        const uint32_t bbase = sb + S_B + (c % 3) * BBUF_SZ;
        #pragma unroll
        for (int kc = 0; kc < 2; kc++) {
            const int cb = kc * 16 + xc;
            float2 f0 = *(const float2*)(xb + xr * XS + cb);
            float2 f1 = *(const float2*)(xb + (xr + 8) * XS + cb);
            float2 f2 = *(const float2*)(xb + xr * XS + cb + 8);
            float2 f3 = *(const float2*)(xb + (xr + 8) * XS + cb + 8);
            uint32_t a[4] = {
                h2u(__floats2half2_rn(f0.x, f0.y)), h2u(__floats2half2_rn(f1.x, f1.y)),
                h2u(__floats2half2_rn(f2.x, f2.y)), h2u(__floats2half2_rn(f3.x, f3.y))};
            #pragma unroll
            for (int nb = 0; nb < 4; nb++) {
                uint32_t bh[4];
                LDSM4(bh[0], bh[1], bh[2], bh[3],
                      bbase + SW64((nb * 16 + lrow) * 64 + kc * 32 + lkb));
                MMA(acc[2 * nb],     a, bh[0], bh[2]);
                MMA(acc[2 * nb + 1], a, bh[1], bh[3]);
            }
        }
    }

    // Write fp32 partial. Tile layout [128][64]; quad writes 32B segments.
    const int r0 = lane >> 2;
    const int c0 = 2 * (lane & 3);
    float* yp = g_Yp + (((size_t)ks * BATCH + b) * 16 + nt) * 8192 + (w * 16) * 64;
    #pragma unroll
    for (int nb = 0; nb < 4; nb++) {
        *(float2*)(yp + r0 * 64 + nb * 16 + c0)       = make_float2(acc[2*nb][0],   acc[2*nb][1]);
        *(float2*)(yp + (r0 + 8) * 64 + nb * 16 + c0) = make_float2(acc[2*nb][2],   acc[2*nb][3]);
        *(float2*)(yp + r0 * 64 + nb * 16 + 8 + c0)       = make_float2(acc[2*nb+1][0], acc[2*nb+1][1]);
        *(float2*)(yp + (r0 + 8) * 64 + nb * 16 + 8 + c0) = make_float2(acc[2*nb+1][2], acc[2*nb+1][3]);
    }
}

// ---------------------------------------------------------------------------
// Stage 2: out[b, n-tile, o-slice] = fp16(sum_ks Yp) @ fp16(A)^T * (1/64)
// grid (16 nt, 16 b, 4 os), 256 thr, 8 warps. Each CTA: 8 o-tiles of 128.
// Partial sum read straight into registers (same lane layout as S1 writer).
// smem (49152): 3 A-bufs of 16384 -> 4 CTAs/SM.
// ---------------------------------------------------------------------------
#define ABUF_SZ 16384
#define SMEM2 49152
#define YSTRIDE ((size_t)BATCH * 16 * 8192)   // between ks partials

__global__ __launch_bounds__(256, 4) void stage2_kernel(float* __restrict__ out) {
    extern __shared__ char smem[];
    const uint32_t sb = smem_u32(smem);
    const int tid = threadIdx.x;
    const int w = tid >> 5;
    const int lane = tid & 31;
    const int nt = blockIdx.x;
    const int b = blockIdx.y;
    const int os = blockIdx.z;

    const unsigned short* ahp = g_Ah + (size_t)b * DOUT * RANK;
    const int lrow = lane & 15;
    const int lkb = (lane >> 4) * 16;
    const int r0 = lane >> 2;
    const int c0 = 2 * (lane & 3);

    // ---- sum 4 Y partials into stage2 a-frags (register-direct) ----
    uint32_t bxh[4][4];
    {
        const float* yp = g_Yp + ((size_t)b * 16 + nt) * 8192 + (w * 16) * 64;
        #pragma unroll
        for (int kc = 0; kc < 4; kc++) {
            #pragma unroll
            for (int h = 0; h < 2; h++) {
                const float* p0 = yp + r0 * 64 + kc * 16 + h * 8 + c0;
                const float* p1 = yp + (r0 + 8) * 64 + kc * 16 + h * 8 + c0;
                float2 s0 = make_float2(0.f, 0.f), s1 = make_float2(0.f, 0.f);
                #pragma unroll
                for (int p = 0; p < KSPLIT; p++) {
                    float2 v0 = *(const float2*)(p0 + p * YSTRIDE);
                    float2 v1 = *(const float2*)(p1 + p * YSTRIDE);
                    s0.x += v0.x; s0.y += v0.y;
                    s1.x += v1.x; s1.y += v1.y;
                }
                bxh[kc][2 * h]     = h2u(__floats2half2_rn(s0.x, s0.y));
                bxh[kc][2 * h + 1] = h2u(__floats2half2_rn(s1.x, s1.y));
            }
        }
    }

    auto issue2 = [&](int i) {
        if (i < 8) {
            const int buf = i % 3;
            const int ot = os * 8 + i;
            #pragma unroll
            for (int t = 0; t < 4; t++) {
                int idx = tid + t * 256;
                int row = idx >> 3, f4 = idx & 7;
                CP_ASYNC16(sb + buf * ABUF_SZ + SW128(row * 128 + f4 * 16),
                           ahp + (size_t)(ot * 128 + row) * RANK + f4 * 8);
            }
        }
        CP_COMMIT();
    };

    issue2(0);
    issue2(1);
    const size_t orow0 = (size_t)b * SEQ + (size_t)nt * 128 + w * 16;
    for (int i = 0; i < 8; i++) {
        CP_WAIT1();
        __syncthreads();
        issue2(i + 2);
        const int ot = os * 8 + i;
        const uint32_t ab = sb + (i % 3) * ABUF_SZ;
        #pragma unroll
        for (int nb = 0; nb < 8; nb++) {
            float d2[2][4];
            #pragma unroll
            for (int h = 0; h < 2; h++)
                #pragma unroll
                for (int j = 0; j < 4; j++) d2[h][j] = 0.f;
            #pragma unroll
            for (int kc = 0; kc < 4; kc++) {
                uint32_t Ah[4];
                LDSM4(Ah[0], Ah[1], Ah[2], Ah[3],
                      ab + SW128((nb * 16 + lrow) * 128 + kc * 32 + lkb));
                MMA(d2[0], bxh[kc], Ah[0], Ah[2]);
                MMA(d2[1], bxh[kc], Ah[1], Ah[3]);
            }
            float* o0 = out + (orow0 + r0) * DOUT + ot * 128 + nb * 16 + c0;
            float* o1 = out + (orow0 + r0 + 8) * DOUT + ot * 128 + nb * 16 + c0;
            *(float2*)o0       = make_float2(d2[0][0] * SCALING, d2[0][1] * SCALING);
            *(float2*)o1       = make_float2(d2[0][2] * SCALING, d2[0][3] * SCALING);
            *(float2*)(o0 + 8) = make_float2(d2[1][0] * SCALING, d2[1][1] * SCALING);
            *(float2*)(o1 + 8) = make_float2(d2[1][2] * SCALING, d2[1][3] * SCALING);
        }
    }
}

// ---------------------------------------------------------------------------
extern "C" void kernel_launch(void* const* d_in, const int* in_sizes, int n_in,
                              void* d_out, int out_size) {
    const float* x   = (const float*)d_in[0];
    const int*   ids = (const int*)  d_in[1];
    const float* A   = (const float*)d_in[2];
    const float* B   = (const float*)d_in[3];
    float* out = (float*)d_out;

    cudaFuncSetAttribute(stage1_kernel, cudaFuncAttributeMaxDynamicSharedMemorySize, SMEM1);
    cudaFuncSetAttribute(stage2_kernel, cudaFuncAttributeMaxDynamicSharedMemorySize, SMEM2);

    dim3 gS(128, BATCH, 2);
    split_kernel<<<gS, 256>>>(A, B, ids);

    dim3 g1(SEQ / 128, BATCH, KSPLIT);
    stage1_kernel<<<g1, 256, SMEM1>>>(x);

    dim3 g2(SEQ / 128, BATCH, OSPLIT);
    stage2_kernel<<<g2, 256, SMEM2>>>(out);

    (void)in_sizes; (void)n_in; (void)out_size;
}

// round 11
// speedup vs baseline: 1.2048x; 1.2048x over previous
#include <cuda_runtime.h>
#include <cuda_fp16.h>
#include <cstdint>

#define BATCH 16
#define SEQ   2048
#define DIN   4096
#define DOUT  4096
#define RANK  64
#define SCALING (1.0f/64.0f)

// ---------------- device scratch (no allocations allowed) -------------------
__device__ unsigned short g_Bh[(size_t)BATCH * RANK * DIN];   // B fp16 [b][r][k]
__device__ unsigned short g_Ah[(size_t)BATCH * DOUT * RANK];  // A fp16 [b][o][r]

// ---------------- helpers ----------------------------------------------------
__device__ __forceinline__ uint32_t smem_u32(const void* p) {
    uint32_t a;
    asm("{ .reg .u64 t; cvta.to.shared.u64 t, %1; cvt.u32.u64 %0, t; }"
        : "=r"(a) : "l"(p));
    return a;
}
#define SW128(o) ((uint32_t)(o) ^ ((((uint32_t)(o)) >> 3) & 0x70))

__device__ __forceinline__ uint32_t h2u(__half2 h) {
    return *reinterpret_cast<uint32_t*>(&h);
}

// cp.async (portable PTX, sm_80+)
#define CP_ASYNC16(dst, src) \
    asm volatile("cp.async.cg.shared.global [%0], [%1], 16;" :: "r"(dst), "l"(src))
#define CP_COMMIT() asm volatile("cp.async.commit_group;" ::: "memory")
#define CP_WAIT0()  asm volatile("cp.async.wait_group 0;" ::: "memory")

// ldmatrix x4 (portable PTX, sm_75+)
#define LDSM4(r0, r1, r2, r3, addr) \
    asm volatile("ldmatrix.sync.aligned.m8n8.x4.shared.b16 {%0,%1,%2,%3}, [%4];" \
        : "=r"(r0), "=r"(r1), "=r"(r2), "=r"(r3) : "r"(addr))

// mma.sync fp16, fp32 accumulate (portable PTX, sm_80+)
#define MMA(d, a, b0v, b1v) \
    asm volatile("mma.sync.aligned.m16n8k16.row.col.f32.f16.f16.f32 " \
        "{%0,%1,%2,%3}, {%4,%5,%6,%7}, {%8,%9}, {%0,%1,%2,%3};" \
        : "+f"((d)[0]), "+f"((d)[1]), "+f"((d)[2]), "+f"((d)[3]) \
        : "r"((a)[0]), "r"((a)[1]), "r"((a)[2]), "r"((a)[3]), "r"(b0v), "r"(b1v))

// ---------------------------------------------------------------------------
// adapter id resolution (int64 or int32 buffer; reads first 64 bytes only)
// ---------------------------------------------------------------------------
__device__ __forceinline__ int resolve_id(const int* raw, int b) {
    bool odd_zero = true;
    #pragma unroll
    for (int i = 1; i < 16; i += 2) odd_zero &= (raw[i] == 0);
    return odd_zero ? raw[2 * b] : raw[b];
}

// ---------------------------------------------------------------------------
// Convert requested A/B adapter slices to fp16.
// grid (128, BATCH, 2), block 256. z=0: B, z=1: A.
// ---------------------------------------------------------------------------
__global__ __launch_bounds__(256) void split_kernel(const float* __restrict__ Am,
                                                    const float* __restrict__ Bm,
                                                    const int* __restrict__ ids) {
    const int b = blockIdx.y;
    const int aid = resolve_id(ids, b);
    const int which = blockIdx.z;
    const size_t i8 = (size_t)blockIdx.x * 256 + threadIdx.x;
    const size_t PER = (size_t)RANK * DIN;
    const float* src = (which ? Am : Bm) + (size_t)aid * PER + i8 * 8;
    unsigned short* dh = (which ? g_Ah : g_Bh) + (size_t)b * PER + i8 * 8;
    float4 v0 = *(const float4*)src;
    float4 v1 = *(const float4*)(src + 4);
    *(uint4*)dh = make_uint4(
        h2u(__floats2half2_rn(v0.x, v0.y)), h2u(__floats2half2_rn(v0.z, v0.w)),
        h2u(__floats2half2_rn(v1.x, v1.y)), h2u(__floats2half2_rn(v1.z, v1.w)));
}

// ---------------------------------------------------------------------------
// Fused LoRA kernel (single-term fp16, CK=64 double-buffered cp.async).
// CTA = (128-n tile, batch). 8 warps, warp owns 16 n-rows.
// Stage 1: Y[16x64] = fp16(x) @ fp16(B)^T  (K=4096 in 64 chunks of 64)
// Stage 2: out = fp16(Y) @ fp16(A)^T * (1/64), 16 o-tiles of 256, direct STG.
// smem (90112 B):
//   stage1: 2 x-bufs [128][68] fp32 @0 (2*34816), 2 B-bufs @69632 (2*8192)
//   stage2: 2 A-bufs @0 (2*32768)
// Correct 2-buffer schedule:
//   issue(0); for c: { WAIT0; BARRIER; issue(c+1); compute(c); }
// At iter c only group c is pending at the wait; the barrier also retires all
// reads of buffer (c+1)&1 (last read at iter c-1), so issue(c+1) is race-free
// and overlaps compute(c).
// ---------------------------------------------------------------------------
#define CK 64
#define NCH (DIN / CK)            // 64
#define XS 68                     // fp32 row stride in words (272B, 16B-aligned)
#define XBUF_SZ (128 * XS * 4)    // 34816
#define BBUF_SZ (64 * CK * 2)     // 8192
#define S_B 69632
#define ABUF_SZ 32768             // 256 o x 64 r fp16
#define SMEM_TOTAL 90112

__global__ __launch_bounds__(256, 2) void fused_kernel(const float* __restrict__ x,
                                                       float* __restrict__ out) {
    extern __shared__ char smem[];
    const uint32_t sb = smem_u32(smem);
    const int tid = threadIdx.x;
    const int w = tid >> 5;
    const int lane = tid & 31;
    const int nt = blockIdx.x;
    const int b = blockIdx.y;

    const float* xp = x + ((size_t)b * SEQ + (size_t)nt * 128) * DIN;
    const unsigned short* bhp = g_Bh + (size_t)b * RANK * DIN;
    const unsigned short* ahp = g_Ah + (size_t)b * DOUT * RANK;

    const int lrow = lane & 15;
    const int lkb = (lane >> 4) * 16;

    // ======================= STAGE 1 ========================================
    float acc[8][4];
    #pragma unroll
    for (int i = 0; i < 8; i++)
        #pragma unroll
        for (int j = 0; j < 4; j++) acc[i][j] = 0.f;

    auto issue1 = [&](int ch) {
        if (ch < NCH) {
            const int buf = ch & 1;
            const int k0 = ch * CK;
            // x: 128 rows x 64 fp32 = 2048 x 16B, 8 per thread
            #pragma unroll
            for (int t = 0; t < 8; t++) {
                int idx = tid + t * 256;
                int row = idx >> 4, f4 = idx & 15;
                CP_ASYNC16(sb + buf * XBUF_SZ + row * (XS * 4) + f4 * 16,
                           xp + (size_t)row * DIN + k0 + f4 * 4);
            }
            // B: 64 rows x 64 fp16 = 512 x 16B, 2 per thread (SW128, 128B rows)
            #pragma unroll
            for (int t = 0; t < 2; t++) {
                int idx = tid + t * 256;
                int row = idx >> 3, f4 = idx & 7;
                CP_ASYNC16(sb + S_B + buf * BBUF_SZ + SW128(row * 128 + f4 * 16),
                           bhp + (size_t)row * DIN + k0 + f4 * 8);
            }
        }
        CP_COMMIT();
    };

    issue1(0);
    const int xr = w * 16 + (lane >> 2);       // a-frag row
    const int xc = (lane & 3) * 2;             // a-frag col base
    for (int c = 0; c < NCH; c++) {
        CP_WAIT0();
        __syncthreads();
        issue1(c + 1);
        const float* xb = (const float*)(smem + (c & 1) * XBUF_SZ);
        const uint32_t bbase = sb + S_B + (c & 1) * BBUF_SZ;
        #pragma unroll
        for (int kc = 0; kc < 4; kc++) {
            const int cb = kc * 16 + xc;
            float2 f0 = *(const float2*)(xb + xr * XS + cb);
            float2 f1 = *(const float2*)(xb + (xr + 8) * XS + cb);
            float2 f2 = *(const float2*)(xb + xr * XS + cb + 8);
            float2 f3 = *(const float2*)(xb + (xr + 8) * XS + cb + 8);
            uint32_t a[4] = {
                h2u(__floats2half2_rn(f0.x, f0.y)), h2u(__floats2half2_rn(f1.x, f1.y)),
                h2u(__floats2half2_rn(f2.x, f2.y)), h2u(__floats2half2_rn(f3.x, f3.y))};
            #pragma unroll
            for (int nb = 0; nb < 4; nb++) {
                uint32_t bh[4];
                LDSM4(bh[0], bh[1], bh[2], bh[3],
                      bbase + SW128((nb * 16 + lrow) * 128 + kc * 32 + lkb));
                MMA(acc[2 * nb],     a, bh[0], bh[2]);
                MMA(acc[2 * nb + 1], a, bh[1], bh[3]);
            }
        }
    }

    // D-frag -> stage2 a-frag (fp16)
    uint32_t bxh[4][4];
    #pragma unroll
    for (int kc = 0; kc < 4; kc++) {
        #pragma unroll
        for (int h = 0; h < 2; h++) {
            float* d = acc[2 * kc + h];
            bxh[kc][2 * h]     = h2u(__floats2half2_rn(d[0], d[1]));
            bxh[kc][2 * h + 1] = h2u(__floats2half2_rn(d[2], d[3]));
        }
    }
    __syncthreads();   // all stage1 smem reads done before stage2 overwrites

    // ======================= STAGE 2 ========================================
    const int r0 = lane >> 2;
    const int c0 = 2 * (lane & 3);
    const size_t orow0 = (size_t)b * SEQ + (size_t)nt * 128 + w * 16;

    auto issue2 = [&](int ot) {
        if (ot < 16) {
            const int buf = ot & 1;
            // A tile: 256 o x 64 r fp16 = 2048 x 16B, 8 per thread
            #pragma unroll
            for (int t = 0; t < 8; t++) {
                int idx = tid + t * 256;
                int row = idx >> 3, f4 = idx & 7;
                CP_ASYNC16(sb + buf * ABUF_SZ + SW128(row * 128 + f4 * 16),
                           ahp + (size_t)(ot * 256 + row) * RANK + f4 * 8);
            }
        }
        CP_COMMIT();
    };

    issue2(0);
    for (int ot = 0; ot < 16; ot++) {
        CP_WAIT0();
        __syncthreads();
        issue2(ot + 1);
        const uint32_t ab = sb + (ot & 1) * ABUF_SZ;
        #pragma unroll
        for (int nb = 0; nb < 16; nb++) {      // o-blocks of 16
            float d2[2][4];
            #pragma unroll
            for (int h = 0; h < 2; h++)
                #pragma unroll
                for (int j = 0; j < 4; j++) d2[h][j] = 0.f;
            #pragma unroll
            for (int kc = 0; kc < 4; kc++) {
                uint32_t Ah[4];
                LDSM4(Ah[0], Ah[1], Ah[2], Ah[3],
                      ab + SW128((nb * 16 + lrow) * 128 + kc * 32 + lkb));
                MMA(d2[0], bxh[kc], Ah[0], Ah[2]);
                MMA(d2[1], bxh[kc], Ah[1], Ah[3]);
            }
            // direct stores: quad-contiguous 32B segments
            float* o0 = out + (orow0 + r0) * DOUT + ot * 256 + nb * 16 + c0;
            float* o1 = out + (orow0 + r0 + 8) * DOUT + ot * 256 + nb * 16 + c0;
            *(float2*)o0       = make_float2(d2[0][0] * SCALING, d2[0][1] * SCALING);
            *(float2*)o1       = make_float2(d2[0][2] * SCALING, d2[0][3] * SCALING);
            *(float2*)(o0 + 8) = make_float2(d2[1][0] * SCALING, d2[1][1] * SCALING);
            *(float2*)(o1 + 8) = make_float2(d2[1][2] * SCALING, d2[1][3] * SCALING);
        }
    }
}

// ---------------------------------------------------------------------------
extern "C" void kernel_launch(void* const* d_in, const int* in_sizes, int n_in,
                              void* d_out, int out_size) {
    const float* x   = (const float*)d_in[0];
    const int*   ids = (const int*)  d_in[1];
    const float* A   = (const float*)d_in[2];
    const float* B   = (const float*)d_in[3];
    float* out = (float*)d_out;

    cudaFuncSetAttribute(fused_kernel, cudaFuncAttributeMaxDynamicSharedMemorySize,
                         SMEM_TOTAL);

    dim3 gS(128, BATCH, 2);
    split_kernel<<<gS, 256>>>(A, B, ids);

    dim3 gF(SEQ / 128, BATCH);
    fused_kernel<<<gF, 256, SMEM_TOTAL>>>(x, out);

    (void)in_sizes; (void)n_in; (void)out_size;
}

// round 12
// speedup vs baseline: 1.2525x; 1.0396x over previous
#include <cuda_runtime.h>
#include <cuda_fp16.h>
#include <cstdint>

#define BATCH 16
#define SEQ   2048
#define DIN   4096
#define DOUT  4096
#define RANK  64
#define SCALING (1.0f/64.0f)

// ---------------- device scratch (no allocations allowed) -------------------
__device__ unsigned short g_Bh[(size_t)BATCH * RANK * DIN];   // B fp16 [b][r][k]
__device__ unsigned short g_Ah[(size_t)BATCH * DOUT * RANK];  // A fp16 [b][o][r]

// ---------------- helpers ----------------------------------------------------
__device__ __forceinline__ uint32_t smem_u32(const void* p) {
    uint32_t a;
    asm("{ .reg .u64 t; cvta.to.shared.u64 t, %1; cvt.u32.u64 %0, t; }"
        : "=r"(a) : "l"(p));
    return a;
}
#define SW64(o)  ((uint32_t)(o) ^ ((((uint32_t)(o)) >> 3) & 0x30))
#define SW128(o) ((uint32_t)(o) ^ ((((uint32_t)(o)) >> 3) & 0x70))

__device__ __forceinline__ uint32_t h2u(__half2 h) {
    return *reinterpret_cast<uint32_t*>(&h);
}

// cp.async (portable PTX, sm_80+)
#define CP_ASYNC16(dst, src) \
    asm volatile("cp.async.cg.shared.global [%0], [%1], 16;" :: "r"(dst), "l"(src))
#define CP_COMMIT() asm volatile("cp.async.commit_group;" ::: "memory")
#define CP_WAIT2()  asm volatile("cp.async.wait_group 2;" ::: "memory")

// ldmatrix x4 (portable PTX, sm_75+)
#define LDSM4(r0, r1, r2, r3, addr) \
    asm volatile("ldmatrix.sync.aligned.m8n8.x4.shared.b16 {%0,%1,%2,%3}, [%4];" \
        : "=r"(r0), "=r"(r1), "=r"(r2), "=r"(r3) : "r"(addr))

// mma.sync fp16, fp32 accumulate (portable PTX, sm_80+)
#define MMA(d, a, b0v, b1v) \
    asm volatile("mma.sync.aligned.m16n8k16.row.col.f32.f16.f16.f32 " \
        "{%0,%1,%2,%3}, {%4,%5,%6,%7}, {%8,%9}, {%0,%1,%2,%3};" \
        : "+f"((d)[0]), "+f"((d)[1]), "+f"((d)[2]), "+f"((d)[3]) \
        : "r"((a)[0]), "r"((a)[1]), "r"((a)[2]), "r"((a)[3]), "r"(b0v), "r"(b1v))

// ---------------------------------------------------------------------------
// adapter id resolution (int64 or int32 buffer; reads first 64 bytes only)
// ---------------------------------------------------------------------------
__device__ __forceinline__ int resolve_id(const int* raw, int b) {
    bool odd_zero = true;
    #pragma unroll
    for (int i = 1; i < 16; i += 2) odd_zero &= (raw[i] == 0);
    return odd_zero ? raw[2 * b] : raw[b];
}

// ---------------------------------------------------------------------------
// Convert requested A/B adapter slices to fp16.
// grid (128, BATCH, 2), block 256. z=0: B, z=1: A.
// ---------------------------------------------------------------------------
__global__ __launch_bounds__(256) void split_kernel(const float* __restrict__ Am,
                                                    const float* __restrict__ Bm,
                                                    const int* __restrict__ ids) {
    const int b = blockIdx.y;
    const int aid = resolve_id(ids, b);
    const int which = blockIdx.z;
    const size_t i8 = (size_t)blockIdx.x * 256 + threadIdx.x;
    const size_t PER = (size_t)RANK * DIN;
    const float* src = (which ? Am : Bm) + (size_t)aid * PER + i8 * 8;
    unsigned short* dh = (which ? g_Ah : g_Bh) + (size_t)b * PER + i8 * 8;
    float4 v0 = *(const float4*)src;
    float4 v1 = *(const float4*)(src + 4);
    *(uint4*)dh = make_uint4(
        h2u(__floats2half2_rn(v0.x, v0.y)), h2u(__floats2half2_rn(v0.z, v0.w)),
        h2u(__floats2half2_rn(v1.x, v1.y)), h2u(__floats2half2_rn(v1.z, v1.w)));
}

// ---------------------------------------------------------------------------
// Fused LoRA kernel (single-term fp16, CK=32, 4-buffer deep pipeline).
// CTA = (128-n tile, batch). 8 warps, warp owns 16 n-rows.
// Stage 1: Y[16x64] = fp16(x) @ fp16(B)^T  (K=4096 in 128 chunks of 32)
// Stage 2: out = fp16(Y/64) @ fp16(A)^T, 32 o-tiles of 128, direct STG.
// smem (98304 B):
//   stage1: 4 x-bufs [128][40] fp32 @0 (4*20480), 4 B-bufs @81920 (4*4096)
//   stage2: 4 A-bufs @0 (4*16384)
// Schedule (issue-before-wait, 4 buffers):
//   issue(0); issue(1);
//   for c: { issue(c+2); WAIT2; BARRIER; compute(c); }
// issue(c+2) writes buf (c+2)%4 == (c-2)%4, whose readers (compute(c-2))
// all finished before barrier(c-1), which every thread at iter c has passed
// -> race-free, and the fill overlaps ~3 chunk-computes before it's needed.
// ---------------------------------------------------------------------------
#define CK 32
#define NCH (DIN / CK)            // 128
#define XS 40                     // fp32 row stride in words (160B)
#define XBUF_SZ (128 * XS * 4)    // 20480
#define BBUF_SZ (64 * CK * 2)     // 4096
#define S_B 81920
#define ABUF_SZ 16384             // 128 o x 64 r fp16
#define SMEM_TOTAL 98304

__global__ __launch_bounds__(256, 2) void fused_kernel(const float* __restrict__ x,
                                                       float* __restrict__ out) {
    extern __shared__ char smem[];
    const uint32_t sb = smem_u32(smem);
    const int tid = threadIdx.x;
    const int w = tid >> 5;
    const int lane = tid & 31;
    const int nt = blockIdx.x;
    const int b = blockIdx.y;

    const float* xp = x + ((size_t)b * SEQ + (size_t)nt * 128) * DIN;
    const unsigned short* bhp = g_Bh + (size_t)b * RANK * DIN;
    const unsigned short* ahp = g_Ah + (size_t)b * DOUT * RANK;

    const int lrow = lane & 15;
    const int lkb = (lane >> 4) * 16;

    // ======================= STAGE 1 ========================================
    float acc[8][4];
    #pragma unroll
    for (int i = 0; i < 8; i++)
        #pragma unroll
        for (int j = 0; j < 4; j++) acc[i][j] = 0.f;

    auto issue1 = [&](int ch) {
        if (ch < NCH) {
            const int buf = ch & 3;
            const int k0 = ch * CK;
            // x: 128 rows x 32 fp32 = 1024 x 16B, 4 per thread
            #pragma unroll
            for (int t = 0; t < 4; t++) {
                int idx = tid + t * 256;
                int row = idx >> 3, f4 = idx & 7;
                CP_ASYNC16(sb + buf * XBUF_SZ + row * (XS * 4) + f4 * 16,
                           xp + (size_t)row * DIN + k0 + f4 * 4);
            }
            // B: 64 rows x 32 fp16 = 256 x 16B, 1 per thread (SW64, 64B rows)
            {
                int row = tid >> 2, f4 = tid & 3;
                CP_ASYNC16(sb + S_B + buf * BBUF_SZ + SW64(row * 64 + f4 * 16),
                           bhp + (size_t)row * DIN + k0 + f4 * 8);
            }
        }
        CP_COMMIT();
    };

    issue1(0);
    issue1(1);
    const int xr = w * 16 + (lane >> 2);       // a-frag row
    const int xc = (lane & 3) * 2;             // a-frag col base
    for (int c = 0; c < NCH; c++) {
        issue1(c + 2);
        CP_WAIT2();
        __syncthreads();
        const float* xb = (const float*)(smem + (c & 3) * XBUF_SZ);
        const uint32_t bbase = sb + S_B + (c & 3) * BBUF_SZ;
        #pragma unroll
        for (int kc = 0; kc < 2; kc++) {
            const int cb = kc * 16 + xc;
            float2 f0 = *(const float2*)(xb + xr * XS + cb);
            float2 f1 = *(const float2*)(xb + (xr + 8) * XS + cb);
            float2 f2 = *(const float2*)(xb + xr * XS + cb + 8);
            float2 f3 = *(const float2*)(xb + (xr + 8) * XS + cb + 8);
            uint32_t a[4] = {
                h2u(__floats2half2_rn(f0.x, f0.y)), h2u(__floats2half2_rn(f1.x, f1.y)),
                h2u(__floats2half2_rn(f2.x, f2.y)), h2u(__floats2half2_rn(f3.x, f3.y))};
            #pragma unroll
            for (int nb = 0; nb < 4; nb++) {
                uint32_t bh[4];
                LDSM4(bh[0], bh[1], bh[2], bh[3],
                      bbase + SW64((nb * 16 + lrow) * 64 + kc * 32 + lkb));
                MMA(acc[2 * nb],     a, bh[0], bh[2]);
                MMA(acc[2 * nb + 1], a, bh[1], bh[3]);
            }
        }
    }

    // D-frag -> stage2 a-frag, with the 1/64 LoRA scaling folded in.
    uint32_t bxh[4][4];
    #pragma unroll
    for (int kc = 0; kc < 4; kc++) {
        #pragma unroll
        for (int h = 0; h < 2; h++) {
            float* d = acc[2 * kc + h];
            bxh[kc][2 * h]     = h2u(__floats2half2_rn(d[0] * SCALING, d[1] * SCALING));
            bxh[kc][2 * h + 1] = h2u(__floats2half2_rn(d[2] * SCALING, d[3] * SCALING));
        }
    }
    __syncthreads();   // all stage1 smem reads done before stage2 overwrites

    // ======================= STAGE 2 ========================================
    const int r0 = lane >> 2;
    const int c0 = 2 * (lane & 3);
    const size_t orow0 = (size_t)b * SEQ + (size_t)nt * 128 + w * 16;

    auto issue2 = [&](int ot) {
        if (ot < 32) {
            const int buf = ot & 3;
            // A tile: 128 o x 64 r fp16 = 1024 x 16B, 4 per thread
            #pragma unroll
            for (int t = 0; t < 4; t++) {
                int idx = tid + t * 256;
                int row = idx >> 3, f4 = idx & 7;
                CP_ASYNC16(sb + buf * ABUF_SZ + SW128(row * 128 + f4 * 16),
                           ahp + (size_t)(ot * 128 + row) * RANK + f4 * 8);
            }
        }
        CP_COMMIT();
    };

    issue2(0);
    issue2(1);
    for (int ot = 0; ot < 32; ot++) {
        issue2(ot + 2);
        CP_WAIT2();
        __syncthreads();
        const uint32_t ab = sb + (ot & 3) * ABUF_SZ;
        #pragma unroll
        for (int nb = 0; nb < 8; nb++) {       // o-blocks of 16
            float d2[2][4];
            #pragma unroll
            for (int h = 0; h < 2; h++)
                #pragma unroll
                for (int j = 0; j < 4; j++) d2[h][j] = 0.f;
            #pragma unroll
            for (int kc = 0; kc < 4; kc++) {
                uint32_t Ah[4];
                LDSM4(Ah[0], Ah[1], Ah[2], Ah[3],
                      ab + SW128((nb * 16 + lrow) * 128 + kc * 32 + lkb));
                MMA(d2[0], bxh[kc], Ah[0], Ah[2]);
                MMA(d2[1], bxh[kc], Ah[1], Ah[3]);
            }
            // direct stores: quad-contiguous 32B segments (scaling pre-folded)
            float* o0 = out + (orow0 + r0) * DOUT + ot * 128 + nb * 16 + c0;
            float* o1 = out + (orow0 + r0 + 8) * DOUT + ot * 128 + nb * 16 + c0;
            *(float2*)o0       = make_float2(d2[0][0], d2[0][1]);
            *(float2*)o1       = make_float2(d2[0][2], d2[0][3]);
            *(float2*)(o0 + 8) = make_float2(d2[1][0], d2[1][1]);
            *(float2*)(o1 + 8) = make_float2(d2[1][2], d2[1][3]);
        }
    }
}

// ---------------------------------------------------------------------------
extern "C" void kernel_launch(void* const* d_in, const int* in_sizes, int n_in,
                              void* d_out, int out_size) {
    const float* x   = (const float*)d_in[0];
    const int*   ids = (const int*)  d_in[1];
    const float* A   = (const float*)d_in[2];
    const float* B   = (const float*)d_in[3];
    float* out = (float*)d_out;

    cudaFuncSetAttribute(fused_kernel, cudaFuncAttributeMaxDynamicSharedMemorySize,
                         SMEM_TOTAL);

    dim3 gS(128, BATCH, 2);
    split_kernel<<<gS, 256>>>(A, B, ids);

    dim3 gF(SEQ / 128, BATCH);
    fused_kernel<<<gF, 256, SMEM_TOTAL>>>(x, out);

    (void)in_sizes; (void)n_in; (void)out_size;
}